// round 15
// baseline (speedup 1.0000x reference)
#include <cuda_runtime.h>

// Profile-HMM forward NLL + KLD -- wavefront, scaled linear domain.
// 512 one-warp blocks. Lane owns k = 2*lane+1, 2*lane+2. Probabilities linear;
// deferred power-of-2 rescale every 8 diagonals via redux.sync (exact).
// Only 2 shuffles/diagonal: neighbor-I is maintained locally from the q
// registers with lane-1's coefficients (identical arithmetic to what lane-1
// computes, incl. replicated phase-1 forcing), so its shuffle is eliminated.

#define FULLMASK 0xffffffffu
#define LN2 0.69314718055994531f

__device__ float g_vb[512];
__device__ unsigned int g_cnt = 0;

__device__ __forceinline__ unsigned warp_max_u32(unsigned v) {
    unsigned r;
    asm volatile("redux.sync.max.u32 %0, %1, 0xffffffff;" : "=r"(r) : "r"(v));
    return r;
}

__global__ void __launch_bounds__(32) phmm_kernel(
    const int*   __restrict__ binput,    // (B, 256)
    const float* __restrict__ trans,     // (B, 65, 7) log-probs (nats)
    const float* __restrict__ emis,      // (B, 64, 4) log-probs (nats)
    const float* __restrict__ mus,       // (B, 16)
    const float* __restrict__ logvars,   // (B, 16)
    float*       __restrict__ out)
{
    constexpr int L = 256;
    constexpr int K = 64;
    const int b    = blockIdx.x;
    const int lane = threadIdx.x;

    __shared__ int    s_co_p[416];       // 64 front-pad + 256 symbols + pad
    __shared__ float2 ep[128];           // [4 symbols][32 lanes] {e1, e2}

    const int* bi = binput + b * L;
#pragma unroll
    for (int i = 0; i < 13; ++i) {
        const int idx = lane + 32 * i;
        int v = 0;
        if (idx >= 64 && idx < 320) v = bi[idx - 64] << 5;
        s_co_p[idx] = v;
    }

    const float* a  = trans + b * 65 * 7;
    const float* em = emis  + b * 64 * 4;

    const int k1 = 2 * lane + 1;
    const float* r0 = a + (k1 - 1) * 7;  // transition row k1-1
    const float* r1 = r0 + 7;            // row k1 (= row k2-1)
    const float* r2 = r1 + 7;            // row k2

    // M2M=0, M2I=1, M2D=2, I2M=3, I2I=4, D2M=5, D2D=6; LOG_Q folded.
    const float aMM1 = expf(r0[0]), aMD1 = expf(r0[2]);
    const float aIM1 = expf(r0[3]), aDM1 = expf(r0[5]), aDD1 = expf(r0[6]);
    const float aMI1 = 0.25f * expf(r1[1]), aII1 = 0.25f * expf(r1[4]);
    const float aMM2 = expf(r1[0]), aMD2 = expf(r1[2]);
    const float aIM2 = expf(r1[3]), aDM2 = expf(r1[5]), aDD2 = expf(r1[6]);
    const float aMI2 = 0.25f * expf(r2[1]), aII2 = 0.25f * expf(r2[4]);
    const float aMI0 = 0.25f * expf(a[1]),  aII0 = 0.25f * expf(a[4]);
    // constant products for the D2 substitution
    const float cDM = aDD2 * aMD1, cDD = aDD2 * aDD1;
    // lane-1's slot2 I-coefficients (for local neighbor-I maintenance)
    const float aMI2n = __shfl_up_sync(FULLMASK, aMI2, 1);
    const float aII2n = __shfl_up_sync(FULLMASK, aII2, 1);

#pragma unroll
    for (int c = 0; c < 4; ++c)
        ep[c * 32 + lane] = make_float2(expf(em[(k1 - 1) * 4 + c]),
                                        expf(em[k1 * 4 + c]));
    __syncwarp();

    float cM1 = 0.f, cI1 = 0.f, cD1 = 0.f, pM1 = 0.f, pI1 = 0.f, pD1 = 0.f;
    float cM2 = 0.f, cI2 = 0.f, cD2 = 0.f;
    const float M00 = 1.152921504606847e18f;    // 1.0 * 2^60
    float inj   = exp2f(-84.26950408889634f);   // e^-100 * 2^60
    float k0I   = inj;
    float mprev = M00;
    int   Sacc  = 60;
    float sc_ap = 1.0f;  int se_ap = 0;

    float nM = (lane == 0) ? M00 : 0.f;
    float nI = (lane == 0) ? inj : 0.f;
    float nD = (lane == 0) ? inj : 0.f;
    float qM = 0.f, qI = 0.f, qD = 0.f;

    int    off_p = s_co_p[65 - k1];
    float2 P     = ep[s_co_p[64 - k1] + lane];
    float  e2c   = 0.0f;

    // ================= phase 1: t = 1..64 (boundary forcing live) ==========
#pragma unroll 4
    for (int t = 1; t <= 64; ++t) {
        const float e1 = P.x;
        const float e2 = e2c;
        const int l1 = t - k1;

        float M1g = e1 * fmaf(aDM1, qD, fmaf(aIM1, qI, aMM1 * qM));
        float I1g = fmaf(aII1, cI1, aMI1 * cM1);
        float D1n = fmaf(aDD1, nD, aMD1 * nM);
        float D2n = fmaf(aMD2, cM1, fmaf(cDM, qM, cDD * qD));
        float M1n = (l1 == 0) ? inj : M1g;
        float I1n = (l1 == 0) ? inj : I1g;

        float M2g = e2 * fmaf(aDM2, pD1, fmaf(aIM2, pI1, aMM2 * pM1));
        float I2g = fmaf(aII2, cI2, aMI2 * cM2);
        float M2n = (l1 == 1) ? inj : M2g;
        float I2n = (l1 == 1) ? inj : I2g;

        cM2 = M2n; cI2 = I2n; cD2 = D2n;
        pM1 = cM1; pI1 = cI1; pD1 = cD1; cM1 = M1n; cI1 = I1n; cD1 = D1n;
        qM = nM; qI = nI; qD = nD;

        k0I = fmaf(aII0, k0I, aMI0 * mprev);
        mprev = inj;

        // local neighbor-I (lane-1's I2 recurrence on exact q inputs)
        nI = fmaf(aII2n, qI, aMI2n * qM);
        if (t == 2 * lane) nI = inj;            // replicate lane-1's forcing
        nM = __shfl_up_sync(FULLMASK, cM2, 1);
        nD = __shfl_up_sync(FULLMASK, cD2, 1);
        if (lane == 0) { nM = mprev; nI = k0I; nD = inj; }

        e2c = P.y;
        P = ep[off_p + lane];
        off_p = s_co_p[t - k1 + 65];

        if ((t & 7) == 0) {
            cM1 *= sc_ap; cI1 *= sc_ap; cD1 *= sc_ap;
            pM1 *= sc_ap; pI1 *= sc_ap; pD1 *= sc_ap;
            cM2 *= sc_ap; cI2 *= sc_ap; cD2 *= sc_ap;
            nM  *= sc_ap; nI  *= sc_ap; nD  *= sc_ap;
            qM  *= sc_ap; qI  *= sc_ap; qD  *= sc_ap;
            k0I *= sc_ap; mprev *= sc_ap; inj *= sc_ap;
            Sacc += se_ap;
            float m = fmaxf(fmaxf(cM1, cM2), fmaxf(cI1, cI2));
            m = fmaxf(m, fmaxf(cD1, cD2));
            m = fmaxf(m, k0I);
            const unsigned mu32 = warp_max_u32(__float_as_uint(m));
            const int E = (int)(mu32 >> 23) & 0xFF;
            int se = 187 - E;
            se = min(max(se, 0), 63);
            se_ap = se;
            sc_ap = __int_as_float((se + 127) << 23);
        }
    }

    // ================= phase 2: t = 65..320 (select-free body) =============
    float cinj = aMI0 * inj;                    // mprev == inj for t >= 2
#pragma unroll 8
    for (int t = 65; t <= L + K; ++t) {
        const float e1 = P.x;
        const float e2 = e2c;

        float M1n = e1 * fmaf(aDM1, qD, fmaf(aIM1, qI, aMM1 * qM));
        float I1n = fmaf(aII1, cI1, aMI1 * cM1);
        float D1n = fmaf(aDD1, nD, aMD1 * nM);
        float D2n = fmaf(aMD2, cM1, fmaf(cDM, qM, cDD * qD));

        float M2n = e2 * fmaf(aDM2, pD1, fmaf(aIM2, pI1, aMM2 * pM1));
        float I2n = fmaf(aII2, cI2, aMI2 * cM2);

        cM2 = M2n; cI2 = I2n; cD2 = D2n;
        pM1 = cM1; pI1 = cI1; pD1 = cD1; cM1 = M1n; cI1 = I1n; cD1 = D1n;
        qM = nM; qI = nI; qD = nD;

        k0I = fmaf(aII0, k0I, cinj);

        nI = fmaf(aII2n, qI, aMI2n * qM);       // local neighbor-I
        nM = __shfl_up_sync(FULLMASK, cM2, 1);
        nD = __shfl_up_sync(FULLMASK, cD2, 1);
        if (lane == 0) { nM = inj; nI = k0I; nD = inj; }

        e2c = P.y;
        P = ep[off_p + lane];
        off_p = s_co_p[t - k1 + 65];

        if ((t & 7) == 0) {
            cM1 *= sc_ap; cI1 *= sc_ap; cD1 *= sc_ap;
            pM1 *= sc_ap; pI1 *= sc_ap; pD1 *= sc_ap;
            cM2 *= sc_ap; cI2 *= sc_ap; cD2 *= sc_ap;
            nM  *= sc_ap; nI  *= sc_ap; nD  *= sc_ap;
            qM  *= sc_ap; qI  *= sc_ap; qD  *= sc_ap;
            k0I *= sc_ap; inj *= sc_ap; cinj *= sc_ap;
            Sacc += se_ap;
            float m = fmaxf(fmaxf(cM1, cM2), fmaxf(cI1, cI2));
            m = fmaxf(m, fmaxf(cD1, cD2));
            m = fmaxf(m, k0I);
            const unsigned mu32 = warp_max_u32(__float_as_uint(m));
            const int E = (int)(mu32 >> 23) & 0xFF;
            int se = 187 - E;
            se = min(max(se, 0), 63);
            se_ap = se;
            sc_ap = __int_as_float((se + 127) << 23);
        }
    }

    // lane 31 slot2 holds (M, I, D) at (L, K)
    const float MF = __shfl_sync(FULLMASK, cM2, 31);
    const float IF = __shfl_sync(FULLMASK, cI2, 31);
    const float DF = __shfl_sync(FULLMASK, cD2, 31);
    const float fM = expf(a[K * 7 + 0]);
    const float fI = expf(a[K * 7 + 3]);
    const float fD = expf(a[K * 7 + 5]);
    const float sum = fmaf(fD, DF, fmaf(fI, IF, fM * MF));
    const float nll = -(log2f(sum) - (float)Sacc) * LN2;

    float term = 0.0f;
    if (lane < 16) {
        const float mu = mus[b * 16 + lane];
        const float lv = logvars[b * 16 + lane];
        term = 1.0f + lv - mu * mu - expf(lv);
    }
#pragma unroll
    for (int o = 16; o > 0; o >>= 1) term += __shfl_xor_sync(FULLMASK, term, o);

    if (lane == 0) g_vb[b] = nll - 0.5f * term;

    // ---- last-block-done final reduction (deterministic fixed-order sum) ----
    __threadfence();
    unsigned int old = 0;
    if (lane == 0) old = atomicAdd(&g_cnt, 1u);
    old = __shfl_sync(FULLMASK, old, 0);
    if (old == gridDim.x - 1) {
        __threadfence();
        float s = 0.0f;
#pragma unroll
        for (int i = 0; i < 16; ++i) s += g_vb[lane + 32 * i];
#pragma unroll
        for (int o = 16; o > 0; o >>= 1) s += __shfl_xor_sync(FULLMASK, s, o);
        if (lane == 0) { out[0] = s * (1.0f / 512.0f); g_cnt = 0; }
    }
}

extern "C" void kernel_launch(void* const* d_in, const int* in_sizes, int n_in,
                              void* d_out, int out_size) {
    const int*   batch_input = (const int*)  d_in[0];
    const float* trans       = (const float*)d_in[1];
    const float* emisp       = (const float*)d_in[2];
    const float* mus         = (const float*)d_in[3];
    const float* logvars     = (const float*)d_in[4];
    (void)in_sizes; (void)n_in; (void)out_size;

    phmm_kernel<<<512, 32>>>(batch_input, trans, emisp, mus, logvars, (float*)d_out);
}

// round 16
// speedup vs baseline: 1.0136x; 1.0136x over previous
#include <cuda_runtime.h>

// Profile-HMM forward NLL + KLD -- wavefront, scaled linear domain.
// 128 CTAs x 128 threads: 4 batch elements per CTA, one per warp, so wid%4
// spreads the four independent warps across all 4 SMSPs (solo-warp SMSPs
// with a lean ~28-slot body). Lane owns k = 2*lane+1, 2*lane+2. Deferred
// power-of-2 rescale every 4 diagonals via redux.sync (exact). Warps are
// fully independent: per-warp smem tables, no block-level sync in the loop.

#define FULLMASK 0xffffffffu
#define LN2 0.69314718055994531f

__device__ float g_vb[512];
__device__ unsigned int g_cnt = 0;

__device__ __forceinline__ unsigned warp_max_u32(unsigned v) {
    unsigned r;
    asm volatile("redux.sync.max.u32 %0, %1, 0xffffffff;" : "=r"(r) : "r"(v));
    return r;
}

__global__ void __launch_bounds__(128) phmm_kernel(
    const int*   __restrict__ binput,    // (B, 256)
    const float* __restrict__ trans,     // (B, 65, 7) log-probs (nats)
    const float* __restrict__ emis,      // (B, 64, 4) log-probs (nats)
    const float* __restrict__ mus,       // (B, 16)
    const float* __restrict__ logvars,   // (B, 16)
    float*       __restrict__ out)
{
    constexpr int L = 256;
    constexpr int K = 64;
    const int w    = threadIdx.x >> 5;
    const int lane = threadIdx.x & 31;
    const int b    = blockIdx.x * 4 + w;

    __shared__ int    s_co_p[4][416];    // per-warp: 64 pad + 256 symbols + pad
    __shared__ float2 ep[4][128];        // per-warp: [4 symbols][32 lanes]

    const int* bi = binput + b * L;
#pragma unroll
    for (int i = 0; i < 13; ++i) {
        const int idx = lane + 32 * i;
        int v = 0;
        if (idx >= 64 && idx < 320) v = bi[idx - 64] << 5;
        s_co_p[w][idx] = v;
    }

    const float* a  = trans + b * 65 * 7;
    const float* em = emis  + b * 64 * 4;

    const int k1 = 2 * lane + 1;
    const float* r0 = a + (k1 - 1) * 7;  // transition row k1-1
    const float* r1 = r0 + 7;            // row k1 (= row k2-1)
    const float* r2 = r1 + 7;            // row k2

    // M2M=0, M2I=1, M2D=2, I2M=3, I2I=4, D2M=5, D2D=6; LOG_Q folded.
    const float aMM1 = expf(r0[0]), aMD1 = expf(r0[2]);
    const float aIM1 = expf(r0[3]), aDM1 = expf(r0[5]), aDD1 = expf(r0[6]);
    const float aMI1 = 0.25f * expf(r1[1]), aII1 = 0.25f * expf(r1[4]);
    const float aMM2 = expf(r1[0]), aMD2 = expf(r1[2]);
    const float aIM2 = expf(r1[3]), aDM2 = expf(r1[5]), aDD2 = expf(r1[6]);
    const float aMI2 = 0.25f * expf(r2[1]), aII2 = 0.25f * expf(r2[4]);
    const float aMI0 = 0.25f * expf(a[1]),  aII0 = 0.25f * expf(a[4]);
    // constant products for the D2 substitution
    const float cDM = aDD2 * aMD1, cDD = aDD2 * aDD1;

#pragma unroll
    for (int c = 0; c < 4; ++c)
        ep[w][c * 32 + lane] = make_float2(expf(em[(k1 - 1) * 4 + c]),
                                           expf(em[k1 * 4 + c]));
    __syncwarp();

    float cM1 = 0.f, cI1 = 0.f, cD1 = 0.f, pM1 = 0.f, pI1 = 0.f, pD1 = 0.f;
    float cM2 = 0.f, cI2 = 0.f, cD2 = 0.f;
    const float M00 = 1.152921504606847e18f;    // 1.0 * 2^60
    float inj   = exp2f(-84.26950408889634f);   // e^-100 * 2^60
    float k0I   = inj;
    float mprev = M00;
    int   Sacc  = 60;
    float sc_ap = 1.0f;  int se_ap = 0;

    float nM = (lane == 0) ? M00 : 0.f;
    float nI = (lane == 0) ? inj : 0.f;
    float nD = (lane == 0) ? inj : 0.f;
    float qM = 0.f, qI = 0.f, qD = 0.f;

    int    off_p = s_co_p[w][65 - k1];
    float2 P     = ep[w][s_co_p[w][64 - k1] + lane];
    float  e2c   = 0.0f;

    // ================= phase 1: t = 1..64 (boundary forcing live) ==========
#pragma unroll 4
    for (int t = 1; t <= 64; ++t) {
        const float e1 = P.x;
        const float e2 = e2c;
        const int l1 = t - k1;

        float M1g = e1 * fmaf(aDM1, qD, fmaf(aIM1, qI, aMM1 * qM));
        float I1g = fmaf(aII1, cI1, aMI1 * cM1);
        float D1n = fmaf(aDD1, nD, aMD1 * nM);
        // D2 via substitution: cD1 == aMD1*qM + aDD1*qD (post-fixup q)
        float D2n = fmaf(aMD2, cM1, fmaf(cDM, qM, cDD * qD));
        float M1n = (l1 == 0) ? inj : M1g;
        float I1n = (l1 == 0) ? inj : I1g;

        float M2g = e2 * fmaf(aDM2, pD1, fmaf(aIM2, pI1, aMM2 * pM1));
        float I2g = fmaf(aII2, cI2, aMI2 * cM2);
        float M2n = (l1 == 1) ? inj : M2g;
        float I2n = (l1 == 1) ? inj : I2g;

        cM2 = M2n; cI2 = I2n; cD2 = D2n;
        pM1 = cM1; pI1 = cI1; pD1 = cD1; cM1 = M1n; cI1 = I1n; cD1 = D1n;
        qM = nM; qI = nI; qD = nD;

        k0I = fmaf(aII0, k0I, aMI0 * mprev);
        mprev = inj;

        nM = __shfl_up_sync(FULLMASK, cM2, 1);
        nI = __shfl_up_sync(FULLMASK, cI2, 1);
        nD = __shfl_up_sync(FULLMASK, cD2, 1);
        if (lane == 0) { nM = mprev; nI = k0I; nD = inj; }

        e2c = P.y;
        P = ep[w][off_p + lane];
        off_p = s_co_p[w][t - k1 + 65];

        if ((t & 3) == 0) {
            cM1 *= sc_ap; cI1 *= sc_ap; cD1 *= sc_ap;
            pM1 *= sc_ap; pI1 *= sc_ap; pD1 *= sc_ap;
            cM2 *= sc_ap; cI2 *= sc_ap; cD2 *= sc_ap;
            nM  *= sc_ap; nI  *= sc_ap; nD  *= sc_ap;
            qM  *= sc_ap; qI  *= sc_ap; qD  *= sc_ap;
            k0I *= sc_ap; mprev *= sc_ap; inj *= sc_ap;
            Sacc += se_ap;
            float m = fmaxf(fmaxf(cM1, cM2), fmaxf(cI1, cI2));
            m = fmaxf(m, fmaxf(cD1, cD2));
            m = fmaxf(m, k0I);
            const unsigned mu32 = warp_max_u32(__float_as_uint(m));
            const int E = (int)(mu32 >> 23) & 0xFF;
            int se = 187 - E;
            se = min(max(se, 0), 63);
            se_ap = se;
            sc_ap = __int_as_float((se + 127) << 23);
        }
    }

    // ================= phase 2: t = 65..320 (select-free body) =============
    float cinj = aMI0 * inj;                    // mprev == inj for t >= 2
#pragma unroll 8
    for (int t = 65; t <= L + K; ++t) {
        const float e1 = P.x;
        const float e2 = e2c;

        float M1n = e1 * fmaf(aDM1, qD, fmaf(aIM1, qI, aMM1 * qM));
        float I1n = fmaf(aII1, cI1, aMI1 * cM1);
        float D1n = fmaf(aDD1, nD, aMD1 * nM);
        float D2n = fmaf(aMD2, cM1, fmaf(cDM, qM, cDD * qD));

        float M2n = e2 * fmaf(aDM2, pD1, fmaf(aIM2, pI1, aMM2 * pM1));
        float I2n = fmaf(aII2, cI2, aMI2 * cM2);

        cM2 = M2n; cI2 = I2n; cD2 = D2n;
        pM1 = cM1; pI1 = cI1; pD1 = cD1; cM1 = M1n; cI1 = I1n; cD1 = D1n;
        qM = nM; qI = nI; qD = nD;

        k0I = fmaf(aII0, k0I, cinj);

        nM = __shfl_up_sync(FULLMASK, cM2, 1);
        nI = __shfl_up_sync(FULLMASK, cI2, 1);
        nD = __shfl_up_sync(FULLMASK, cD2, 1);
        if (lane == 0) { nM = inj; nI = k0I; nD = inj; }

        e2c = P.y;
        P = ep[w][off_p + lane];
        off_p = s_co_p[w][t - k1 + 65];

        if ((t & 3) == 0) {
            cM1 *= sc_ap; cI1 *= sc_ap; cD1 *= sc_ap;
            pM1 *= sc_ap; pI1 *= sc_ap; pD1 *= sc_ap;
            cM2 *= sc_ap; cI2 *= sc_ap; cD2 *= sc_ap;
            nM  *= sc_ap; nI  *= sc_ap; nD  *= sc_ap;
            qM  *= sc_ap; qI  *= sc_ap; qD  *= sc_ap;
            k0I *= sc_ap; inj *= sc_ap; cinj *= sc_ap;
            Sacc += se_ap;
            float m = fmaxf(fmaxf(cM1, cM2), fmaxf(cI1, cI2));
            m = fmaxf(m, fmaxf(cD1, cD2));
            m = fmaxf(m, k0I);
            const unsigned mu32 = warp_max_u32(__float_as_uint(m));
            const int E = (int)(mu32 >> 23) & 0xFF;
            int se = 187 - E;
            se = min(max(se, 0), 63);
            se_ap = se;
            sc_ap = __int_as_float((se + 127) << 23);
        }
    }

    // lane 31 slot2 holds (M, I, D) at (L, K)
    const float MF = __shfl_sync(FULLMASK, cM2, 31);
    const float IF = __shfl_sync(FULLMASK, cI2, 31);
    const float DF = __shfl_sync(FULLMASK, cD2, 31);
    const float fM = expf(a[K * 7 + 0]);
    const float fI = expf(a[K * 7 + 3]);
    const float fD = expf(a[K * 7 + 5]);
    const float sum = fmaf(fD, DF, fmaf(fI, IF, fM * MF));
    const float nll = -(log2f(sum) - (float)Sacc) * LN2;

    float term = 0.0f;
    if (lane < 16) {
        const float mu = mus[b * 16 + lane];
        const float lv = logvars[b * 16 + lane];
        term = 1.0f + lv - mu * mu - expf(lv);
    }
#pragma unroll
    for (int o = 16; o > 0; o >>= 1) term += __shfl_xor_sync(FULLMASK, term, o);

    if (lane == 0) g_vb[b] = nll - 0.5f * term;

    // ---- last-warp-done final reduction (deterministic fixed-order sum) ----
    __threadfence();
    unsigned int old = 0;
    if (lane == 0) old = atomicAdd(&g_cnt, 1u);
    old = __shfl_sync(FULLMASK, old, 0);
    if (old == 4u * gridDim.x - 1u) {
        __threadfence();
        float s = 0.0f;
#pragma unroll
        for (int i = 0; i < 16; ++i) s += g_vb[lane + 32 * i];
#pragma unroll
        for (int o = 16; o > 0; o >>= 1) s += __shfl_xor_sync(FULLMASK, s, o);
        if (lane == 0) { out[0] = s * (1.0f / 512.0f); g_cnt = 0; }
    }
}

extern "C" void kernel_launch(void* const* d_in, const int* in_sizes, int n_in,
                              void* d_out, int out_size) {
    const int*   batch_input = (const int*)  d_in[0];
    const float* trans       = (const float*)d_in[1];
    const float* emisp       = (const float*)d_in[2];
    const float* mus         = (const float*)d_in[3];
    const float* logvars     = (const float*)d_in[4];
    (void)in_sizes; (void)n_in; (void)out_size;

    phmm_kernel<<<128, 128>>>(batch_input, trans, emisp, mus, logvars, (float*)d_out);
}

// round 17
// speedup vs baseline: 1.0156x; 1.0020x over previous
#include <cuda_runtime.h>

// Profile-HMM forward NLL + KLD -- wavefront, scaled linear domain.
// 512 one-warp blocks. Lane owns k = 2*lane+1, 2*lane+2. Probabilities linear;
// deferred power-of-2 rescale every 4 diagonals via redux.sync (exact).
// Z-SHUFFLE: the producer lane pre-combines the consumer's M/D neighbor dot
// products with the consumer's row coefficients (== producer's r2 row), so
// only 2 shuffles/diagonal are needed and the post-shuffle work is 1 mul.

#define FULLMASK 0xffffffffu
#define LN2 0.69314718055994531f

__device__ float g_vb[512];
__device__ unsigned int g_cnt = 0;

__device__ __forceinline__ unsigned warp_max_u32(unsigned v) {
    unsigned r;
    asm volatile("redux.sync.max.u32 %0, %1, 0xffffffff;" : "=r"(r) : "r"(v));
    return r;
}

__global__ void __launch_bounds__(32) phmm_kernel(
    const int*   __restrict__ binput,    // (B, 256)
    const float* __restrict__ trans,     // (B, 65, 7) log-probs (nats)
    const float* __restrict__ emis,      // (B, 64, 4) log-probs (nats)
    const float* __restrict__ mus,       // (B, 16)
    const float* __restrict__ logvars,   // (B, 16)
    float*       __restrict__ out)
{
    constexpr int L = 256;
    constexpr int K = 64;
    const int b    = blockIdx.x;
    const int lane = threadIdx.x;

    __shared__ int    s_co_p[416];       // 64 front-pad + 256 symbols + pad
    __shared__ float2 ep[128];           // [4 symbols][32 lanes] {e1, e2}

    const int* bi = binput + b * L;
#pragma unroll
    for (int i = 0; i < 13; ++i) {
        const int idx = lane + 32 * i;
        int v = 0;
        if (idx >= 64 && idx < 320) v = bi[idx - 64] << 5;
        s_co_p[idx] = v;
    }

    const float* a  = trans + b * 65 * 7;
    const float* em = emis  + b * 64 * 4;

    const int k1 = 2 * lane + 1;
    const float* r0 = a + (k1 - 1) * 7;  // transition row k1-1
    const float* r1 = r0 + 7;            // row k1 (= row k2-1)
    const float* r2 = r1 + 7;            // row k2

    // M2M=0, M2I=1, M2D=2, I2M=3, I2I=4, D2M=5, D2D=6; LOG_Q folded.
    const float aMM1 = expf(r0[0]), aMD1 = expf(r0[2]);
    const float aIM1 = expf(r0[3]), aDM1 = expf(r0[5]), aDD1 = expf(r0[6]);
    const float aMI1 = 0.25f * expf(r1[1]), aII1 = 0.25f * expf(r1[4]);
    const float aMM2 = expf(r1[0]), aMD2 = expf(r1[2]);
    const float aIM2 = expf(r1[3]), aDM2 = expf(r1[5]), aDD2 = expf(r1[6]);
    const float aMI2 = 0.25f * expf(r2[1]), aII2 = 0.25f * expf(r2[4]);
    const float aMI0 = 0.25f * expf(a[1]),  aII0 = 0.25f * expf(a[4]);
    // producer-side coefficients: OUR r2 row is the NEXT lane's r0 row
    const float aMMz = expf(r2[0]), aMDz = expf(r2[2]);
    const float aIMz = expf(r2[3]), aDMz = expf(r2[5]), aDDz = expf(r2[6]);
    // lane-0 fixup constants (k0 column has M=D=inj for t>=1)
    const float sMMD = aMM1 + aDM1;      // zM0 = aIM1*k0I + sMMD*inj
    const float sMDD = aMD1 + aDD1;      // zD0 = sMDD*inj

#pragma unroll
    for (int c = 0; c < 4; ++c)
        ep[c * 32 + lane] = make_float2(expf(em[(k1 - 1) * 4 + c]),
                                        expf(em[k1 * 4 + c]));
    __syncwarp();

    float cM1 = 0.f, cI1 = 0.f, cD1 = 0.f, pM1 = 0.f, pI1 = 0.f, pD1 = 0.f;
    float cM2 = 0.f, cI2 = 0.f, cD2 = 0.f;
    const float M00 = 1.152921504606847e18f;    // 1.0 * 2^60
    float inj   = exp2f(-84.26950408889634f);   // e^-100 * 2^60
    float k0I   = inj;
    float mprev = M00;
    int   Sacc  = 60;
    float sc_ap = 1.0f;  int se_ap = 0;
    float cMinj = sMMD * inj;                   // lane-0 zM constant part
    float cDinj = sMDD * inj;                   // lane-0 zD value

    // primed z carries (gen-0 k0-column values on lane 0; dead elsewhere)
    float qzM = 0.f;                                        // for M1 at t=1 (dead/forced)
    float nzM = (lane == 0) ? fmaf(aMM1, M00, (aIM1 + aDM1) * inj) : 0.f;
    float nzD = (lane == 0) ? fmaf(aMD1, M00, aDD1 * inj)          : 0.f;

    int    off_p = s_co_p[65 - k1];
    float2 P     = ep[s_co_p[64 - k1] + lane];
    float  e2c   = 0.0f;

    // ================= phase 1: t = 1..64 (boundary forcing live) ==========
#pragma unroll 4
    for (int t = 1; t <= 64; ++t) {
        const float e1 = P.x;
        const float e2 = e2c;
        const int l1 = t - k1;

        float M1g = e1 * qzM;
        float I1g = fmaf(aII1, cI1, aMI1 * cM1);
        float D1n = nzD;
        float D2n = fmaf(aMD2, cM1, aDD2 * cD1);
        float M1n = (l1 == 0) ? inj : M1g;
        float I1n = (l1 == 0) ? inj : I1g;

        float M2g = e2 * fmaf(aDM2, pD1, fmaf(aIM2, pI1, aMM2 * pM1));
        float I2g = fmaf(aII2, cI2, aMI2 * cM2);
        float M2n = (l1 == 1) ? inj : M2g;
        float I2n = (l1 == 1) ? inj : I2g;

        cM2 = M2n; cI2 = I2n; cD2 = D2n;
        pM1 = cM1; pI1 = cI1; pD1 = cD1; cM1 = M1n; cI1 = I1n; cD1 = D1n;
        qzM = nzM;

        k0I = fmaf(aII0, k0I, aMI0 * mprev);
        mprev = inj;

        // producer-side combined neighbor values (consumer = lane+1)
        float zM = fmaf(aDMz, cD2, fmaf(aIMz, cI2, aMMz * cM2));
        float zD = fmaf(aDDz, cD2, aMDz * cM2);
        nzM = __shfl_up_sync(FULLMASK, zM, 1);
        nzD = __shfl_up_sync(FULLMASK, zD, 1);
        if (lane == 0) { nzM = fmaf(aIM1, k0I, cMinj); nzD = cDinj; }

        e2c = P.y;
        P = ep[off_p + lane];
        off_p = s_co_p[t - k1 + 65];

        if ((t & 3) == 0) {
            cM1 *= sc_ap; cI1 *= sc_ap; cD1 *= sc_ap;
            pM1 *= sc_ap; pI1 *= sc_ap; pD1 *= sc_ap;
            cM2 *= sc_ap; cI2 *= sc_ap; cD2 *= sc_ap;
            qzM *= sc_ap; nzM *= sc_ap; nzD *= sc_ap;
            k0I *= sc_ap; mprev *= sc_ap; inj *= sc_ap;
            cMinj *= sc_ap; cDinj *= sc_ap;
            Sacc += se_ap;
            float m = fmaxf(fmaxf(cM1, cM2), fmaxf(cI1, cI2));
            m = fmaxf(m, fmaxf(cD1, cD2));
            m = fmaxf(m, k0I);
            const unsigned mu32 = warp_max_u32(__float_as_uint(m));
            const int E = (int)(mu32 >> 23) & 0xFF;
            int se = 187 - E;
            se = min(max(se, 0), 63);
            se_ap = se;
            sc_ap = __int_as_float((se + 127) << 23);
        }
    }

    // ================= phase 2: t = 65..320 (select-free body) =============
    float cinj = aMI0 * inj;                    // mprev == inj for t >= 2
#pragma unroll 8
    for (int t = 65; t <= L + K; ++t) {
        const float e1 = P.x;
        const float e2 = e2c;

        float M1n = e1 * qzM;
        float I1n = fmaf(aII1, cI1, aMI1 * cM1);
        float D1n = nzD;
        float D2n = fmaf(aMD2, cM1, aDD2 * cD1);

        float M2n = e2 * fmaf(aDM2, pD1, fmaf(aIM2, pI1, aMM2 * pM1));
        float I2n = fmaf(aII2, cI2, aMI2 * cM2);

        cM2 = M2n; cI2 = I2n; cD2 = D2n;
        pM1 = cM1; pI1 = cI1; pD1 = cD1; cM1 = M1n; cI1 = I1n; cD1 = D1n;
        qzM = nzM;

        k0I = fmaf(aII0, k0I, cinj);

        float zM = fmaf(aDMz, cD2, fmaf(aIMz, cI2, aMMz * cM2));
        float zD = fmaf(aDDz, cD2, aMDz * cM2);
        nzM = __shfl_up_sync(FULLMASK, zM, 1);
        nzD = __shfl_up_sync(FULLMASK, zD, 1);
        if (lane == 0) { nzM = fmaf(aIM1, k0I, cMinj); nzD = cDinj; }

        e2c = P.y;
        P = ep[off_p + lane];
        off_p = s_co_p[t - k1 + 65];

        if ((t & 3) == 0) {
            cM1 *= sc_ap; cI1 *= sc_ap; cD1 *= sc_ap;
            pM1 *= sc_ap; pI1 *= sc_ap; pD1 *= sc_ap;
            cM2 *= sc_ap; cI2 *= sc_ap; cD2 *= sc_ap;
            qzM *= sc_ap; nzM *= sc_ap; nzD *= sc_ap;
            k0I *= sc_ap; inj *= sc_ap; cinj *= sc_ap;
            cMinj *= sc_ap; cDinj *= sc_ap;
            Sacc += se_ap;
            float m = fmaxf(fmaxf(cM1, cM2), fmaxf(cI1, cI2));
            m = fmaxf(m, fmaxf(cD1, cD2));
            m = fmaxf(m, k0I);
            const unsigned mu32 = warp_max_u32(__float_as_uint(m));
            const int E = (int)(mu32 >> 23) & 0xFF;
            int se = 187 - E;
            se = min(max(se, 0), 63);
            se_ap = se;
            sc_ap = __int_as_float((se + 127) << 23);
        }
    }

    // lane 31 slot2 holds (M, I, D) at (L, K)
    const float MF = __shfl_sync(FULLMASK, cM2, 31);
    const float IF = __shfl_sync(FULLMASK, cI2, 31);
    const float DF = __shfl_sync(FULLMASK, cD2, 31);
    const float fM = expf(a[K * 7 + 0]);
    const float fI = expf(a[K * 7 + 3]);
    const float fD = expf(a[K * 7 + 5]);
    const float sum = fmaf(fD, DF, fmaf(fI, IF, fM * MF));
    const float nll = -(log2f(sum) - (float)Sacc) * LN2;

    float term = 0.0f;
    if (lane < 16) {
        const float mu = mus[b * 16 + lane];
        const float lv = logvars[b * 16 + lane];
        term = 1.0f + lv - mu * mu - expf(lv);
    }
#pragma unroll
    for (int o = 16; o > 0; o >>= 1) term += __shfl_xor_sync(FULLMASK, term, o);

    if (lane == 0) g_vb[b] = nll - 0.5f * term;

    // ---- last-block-done final reduction (deterministic fixed-order sum) ----
    __threadfence();
    unsigned int old = 0;
    if (lane == 0) old = atomicAdd(&g_cnt, 1u);
    old = __shfl_sync(FULLMASK, old, 0);
    if (old == gridDim.x - 1) {
        __threadfence();
        float s = 0.0f;
#pragma unroll
        for (int i = 0; i < 16; ++i) s += g_vb[lane + 32 * i];
#pragma unroll
        for (int o = 16; o > 0; o >>= 1) s += __shfl_xor_sync(FULLMASK, s, o);
        if (lane == 0) { out[0] = s * (1.0f / 512.0f); g_cnt = 0; }
    }
}

extern "C" void kernel_launch(void* const* d_in, const int* in_sizes, int n_in,
                              void* d_out, int out_size) {
    const int*   batch_input = (const int*)  d_in[0];
    const float* trans       = (const float*)d_in[1];
    const float* emisp       = (const float*)d_in[2];
    const float* mus         = (const float*)d_in[3];
    const float* logvars     = (const float*)d_in[4];
    (void)in_sizes; (void)n_in; (void)out_size;

    phmm_kernel<<<512, 32>>>(batch_input, trans, emisp, mus, logvars, (float*)d_out);
}